// round 1
// baseline (speedup 1.0000x reference)
#include <cuda_runtime.h>
#include <cuda_bf16.h>
#include <math.h>

#define H 512
#define W 512
#define B 32
#define CELL 16
#define NC 32            // cells per dim
#define NB 31            // blocks per dim
#define ORI 6
#define BLK_FEAT 24      // 2*2*ORI
#define FEAT_PER_IMG (NB*NB*BLK_FEAT)

// scratch: per-cell histograms, (B, 32, 32, 6)
__device__ float g_cells[B * NC * NC * ORI];

// ---------------------------------------------------------------------------
// Kernel A: gray -> gradients -> orientation bin -> cell histogram
// one 256-thread CTA per 16x16 cell; 18x18 gray halo tile in smem
// ---------------------------------------------------------------------------
__global__ __launch_bounds__(256) void hog_cells_kernel(
    const float* __restrict__ x, float* __restrict__ cells)
{
    const int cx = blockIdx.x;   // cell col
    const int cy = blockIdx.y;   // cell row
    const int b  = blockIdx.z;   // image

    __shared__ float tile[18 * 18];
    __shared__ float hist[ORI];

    const int tid = threadIdx.x;
    if (tid < ORI) hist[tid] = 0.0f;

    const float* xb = x + (size_t)b * 3 * H * W;

    // load 18x18 gray tile (halo of 1), OOB -> 0
    #pragma unroll
    for (int idx = tid; idx < 324; idx += 256) {
        const int lr = idx / 18;
        const int lc = idx - lr * 18;
        const int r = cy * CELL - 1 + lr;
        const int c = cx * CELL - 1 + lc;
        float g = 0.0f;
        if (r >= 0 && r < H && c >= 0 && c < W) {
            const int p = r * W + c;
            g = 0.299f * __ldg(xb + p)
              + 0.587f * __ldg(xb + H * W + p)
              + 0.114f * __ldg(xb + 2 * H * W + p);
        }
        tile[idx] = g;
    }
    __syncthreads();

    const int ty = tid >> 4;
    const int tx = tid & 15;
    const int lr = ty + 1;
    const int lc = tx + 1;
    const int r = cy * CELL + ty;
    const int c = cx * CELL + tx;

    // central differences with zeroed borders (skimage semantics)
    float gr = (r > 0 && r < H - 1)
                 ? tile[(lr + 1) * 18 + lc] - tile[(lr - 1) * 18 + lc] : 0.0f;
    float gc = (c > 0 && c < W - 1)
                 ? tile[lr * 18 + lc + 1] - tile[lr * 18 + lc - 1] : 0.0f;

    const float mag = sqrtf(gr * gr + gc * gc);

    // orientation bin = floor((degrees(atan2(gr,gc)) mod 180) / 30), clipped.
    // Canonicalize (X,Y)=(gc,gr) to upper half-plane (mod-180 invariant),
    // then count boundary crossings via cross-product sign tests.
    float X = gc, Y = gr;
    if (Y < 0.0f || (Y == 0.0f && X < 0.0f)) { X = -X; Y = -Y; }
    const float C30 = 0.8660254037844386f;  // cos30 = sin60
    int bin = 0;
    bin += (C30  * Y - 0.5f * X >= 0.0f);   // >= 30 deg
    bin += (0.5f * Y - C30  * X >= 0.0f);   // >= 60
    bin += (          -        X >= 0.0f);  // >= 90
    bin += (-0.5f * Y - C30 * X >= 0.0f);   // >= 120
    bin += (-C30  * Y - 0.5f * X >= 0.0f);  // >= 150

    atomicAdd(&hist[bin], mag);
    __syncthreads();

    if (tid < ORI)
        cells[(((size_t)b * NC + cy) * NC + cx) * ORI + tid] =
            hist[tid] * (1.0f / (CELL * CELL));
}

// ---------------------------------------------------------------------------
// Kernel B: 2x2-cell blocks, L2-Hys normalization, write descriptor
// one warp per HOG block; lanes 0..23 hold the 24 block values
// ---------------------------------------------------------------------------
__global__ __launch_bounds__(256) void hog_blocks_kernel(
    const float* __restrict__ cells, float* __restrict__ out)
{
    const int gwarp = (blockIdx.x * blockDim.x + threadIdx.x) >> 5;
    const int lane  = threadIdx.x & 31;
    const int total = B * NB * NB;
    if (gwarp >= total) return;

    const int b  = gwarp / (NB * NB);
    const int ij = gwarp - b * (NB * NB);
    const int i  = ij / NB;
    const int j  = ij - i * NB;

    float v = 0.0f;
    if (lane < BLK_FEAT) {
        const int ci = lane / 12;          // which cell row in block
        const int cj = (lane / ORI) & 1;   // which cell col in block
        const int o  = lane % ORI;
        v = __ldg(&cells[(((size_t)b * NC + (i + ci)) * NC + (j + cj)) * ORI + o]);
    }

    const float EPS2 = 1e-10f;  // (1e-5)^2

    float ss = v * v;
    #pragma unroll
    for (int s = 16; s; s >>= 1) ss += __shfl_xor_sync(0xffffffffu, ss, s);
    const float n1 = sqrtf(ss + EPS2);
    float v1 = fminf(v / n1, 0.2f);
    if (lane >= BLK_FEAT) v1 = 0.0f;

    float ss2 = v1 * v1;
    #pragma unroll
    for (int s = 16; s; s >>= 1) ss2 += __shfl_xor_sync(0xffffffffu, ss2, s);
    const float n2 = sqrtf(ss2 + EPS2);

    if (lane < BLK_FEAT)
        out[(size_t)gwarp * BLK_FEAT + lane] = v1 / n2;
}

// ---------------------------------------------------------------------------
extern "C" void kernel_launch(void* const* d_in, const int* in_sizes, int n_in,
                              void* d_out, int out_size)
{
    const float* x = (const float*)d_in[0];
    float* out = (float*)d_out;

    float* cells;
    cudaGetSymbolAddress((void**)&cells, g_cells);

    dim3 gridA(NC, NC, B);
    hog_cells_kernel<<<gridA, 256>>>(x, cells);

    const int total_warps = B * NB * NB;              // 30752
    const int blocksB = (total_warps * 32 + 255) / 256;
    hog_blocks_kernel<<<blocksB, 256>>>(cells, out);
}

// round 2
// speedup vs baseline: 4.0010x; 4.0010x over previous
#include <cuda_runtime.h>
#include <cuda_bf16.h>
#include <math.h>

#define H 512
#define W 512
#define B 32
#define CELL 16
#define NC 32            // cells per dim
#define NB 31            // blocks per dim
#define ORI 6
#define BLK_FEAT 24      // 2*2*ORI
#define HWsz (H*W)

// scratch: per-cell histograms, (B, 32, 32, 6)
__device__ float g_cells[B * NC * NC * ORI];

// ---------------------------------------------------------------------------
// Kernel A: strip-based. One 512-thread CTA per (image, cell-row).
// Loads 18 gray rows (16 + halo) into smem with perfectly coalesced LDGs,
// computes central-difference gradients, bins orientation with cross-product
// sign tests, accumulates register-resident 6-bin histograms, reduces within
// 16-lane column groups via shfl. No atomics.
// ---------------------------------------------------------------------------
__global__ __launch_bounds__(512) void hog_cells_kernel(
    const float* __restrict__ x, float* __restrict__ cells)
{
    const int strip = blockIdx.x;   // cell row 0..31
    const int b     = blockIdx.y;   // image

    __shared__ float sm[18][512];

    const int c = threadIdx.x;      // column 0..511
    const float* xb = x + (size_t)b * 3 * HWsz;
    const int r0 = strip * CELL - 1;

    // load 18 rows of grayscale (OOB rows -> 0). 54 independent coalesced LDGs.
    #pragma unroll
    for (int i = 0; i < 18; i++) {
        const int r = r0 + i;
        float g = 0.0f;
        if (r >= 0 && r < H) {
            const int p = r * W + c;
            g = 0.299f * __ldg(xb + p)
              + 0.587f * __ldg(xb + HWsz + p)
              + 0.114f * __ldg(xb + 2 * HWsz + p);
        }
        sm[i][c] = g;
    }
    __syncthreads();

    float h0 = 0.f, h1 = 0.f, h2 = 0.f, h3 = 0.f, h4 = 0.f, h5 = 0.f;

    const bool cok = (c > 0) && (c < W - 1);
    const float C30 = 0.8660254037844386f;  // cos 30

    #pragma unroll
    for (int i = 0; i < 16; i++) {
        const int r = strip * CELL + i;
        // central differences with zeroed borders (skimage semantics)
        const float gr = (r > 0 && r < H - 1) ? sm[i + 2][c] - sm[i][c] : 0.0f;
        const float gc = cok ? sm[i + 1][c + 1] - sm[i + 1][c - 1] : 0.0f;

        const float mag = sqrtf(gr * gr + gc * gc);

        // bin = floor((degrees(atan2(gr,gc)) mod 180)/30), via boundary
        // cross-product sign tests after canonicalizing to upper half-plane.
        float X = gc, Y = gr;
        if (Y < 0.0f || (Y == 0.0f && X < 0.0f)) { X = -X; Y = -Y; }
        int bin = 0;
        bin += (C30  * Y - 0.5f * X >= 0.0f);   // >= 30 deg
        bin += (0.5f * Y - C30  * X >= 0.0f);   // >= 60
        bin += (          -        X >= 0.0f);  // >= 90
        bin += (-0.5f * Y - C30 * X >= 0.0f);   // >= 120
        bin += (-C30  * Y - 0.5f * X >= 0.0f);  // >= 150

        h0 += (bin == 0) ? mag : 0.0f;
        h1 += (bin == 1) ? mag : 0.0f;
        h2 += (bin == 2) ? mag : 0.0f;
        h3 += (bin == 3) ? mag : 0.0f;
        h4 += (bin == 4) ? mag : 0.0f;
        h5 += (bin == 5) ? mag : 0.0f;
    }

    // reduce across the 16 lanes of each column group (xor 8,4,2,1 stays
    // within each 16-lane half of the warp)
    #pragma unroll
    for (int s = 8; s; s >>= 1) {
        h0 += __shfl_xor_sync(0xffffffffu, h0, s);
        h1 += __shfl_xor_sync(0xffffffffu, h1, s);
        h2 += __shfl_xor_sync(0xffffffffu, h2, s);
        h3 += __shfl_xor_sync(0xffffffffu, h3, s);
        h4 += __shfl_xor_sync(0xffffffffu, h4, s);
        h5 += __shfl_xor_sync(0xffffffffu, h5, s);
    }

    if ((c & 15) == 0) {
        const int cellx = c >> 4;
        float* dst = cells + (((size_t)b * NC + strip) * NC + cellx) * ORI;
        const float inv = 1.0f / (CELL * CELL);
        dst[0] = h0 * inv;
        dst[1] = h1 * inv;
        dst[2] = h2 * inv;
        dst[3] = h3 * inv;
        dst[4] = h4 * inv;
        dst[5] = h5 * inv;
    }
}

// ---------------------------------------------------------------------------
// Kernel B: one THREAD per HOG block. 24 values in registers, L2-resident
// cell reads via float2, register reductions, float2 stores.
// ---------------------------------------------------------------------------
__global__ __launch_bounds__(256) void hog_blocks_kernel(
    const float* __restrict__ cells, float* __restrict__ out)
{
    const int t = blockIdx.x * blockDim.x + threadIdx.x;
    const int total = B * NB * NB;
    if (t >= total) return;

    const int b  = t / (NB * NB);
    const int ij = t - b * (NB * NB);
    const int i  = ij / NB;
    const int j  = ij - i * NB;

    // cells (b, i, j..j+1, 6) are 12 contiguous floats; same for row i+1.
    const float2* p0 = (const float2*)(cells + (((size_t)b * NC + i)     * NC + j) * ORI);
    const float2* p1 = (const float2*)(cells + (((size_t)b * NC + i + 1) * NC + j) * ORI);

    float v[24];
    #pragma unroll
    for (int k = 0; k < 6; k++) {
        const float2 a = __ldg(p0 + k);
        v[2 * k]     = a.x;
        v[2 * k + 1] = a.y;
    }
    #pragma unroll
    for (int k = 0; k < 6; k++) {
        const float2 a = __ldg(p1 + k);
        v[12 + 2 * k]     = a.x;
        v[12 + 2 * k + 1] = a.y;
    }

    const float EPS2 = 1e-10f;  // (1e-5)^2

    float ss = 0.0f;
    #pragma unroll
    for (int k = 0; k < 24; k++) ss += v[k] * v[k];
    const float inv_n1 = 1.0f / sqrtf(ss + EPS2);

    float ss2 = 0.0f;
    #pragma unroll
    for (int k = 0; k < 24; k++) {
        v[k] = fminf(v[k] * inv_n1, 0.2f);
        ss2 += v[k] * v[k];
    }
    const float inv_n2 = 1.0f / sqrtf(ss2 + EPS2);

    float2* o = (float2*)(out + (size_t)t * BLK_FEAT);
    #pragma unroll
    for (int k = 0; k < 12; k++) {
        float2 w;
        w.x = v[2 * k]     * inv_n2;
        w.y = v[2 * k + 1] * inv_n2;
        o[k] = w;
    }
}

// ---------------------------------------------------------------------------
extern "C" void kernel_launch(void* const* d_in, const int* in_sizes, int n_in,
                              void* d_out, int out_size)
{
    const float* x = (const float*)d_in[0];
    float* out = (float*)d_out;

    float* cells;
    cudaGetSymbolAddress((void**)&cells, g_cells);

    dim3 gridA(NC, B);
    hog_cells_kernel<<<gridA, 512>>>(x, cells);

    const int total = B * NB * NB;                 // 30752
    hog_blocks_kernel<<<(total + 255) / 256, 256>>>(cells, out);
}